// round 5
// baseline (speedup 1.0000x reference)
#include <cuda_runtime.h>

// Histogram2d: x[32,16384,64] f32 in [0,1) -> hist[32,128,64] * weights[128,64]
//
// Single fused kernel. Per-thread private u8 histograms in SMEM with a
// bank-aligned layout (lane l always hits bank l -> conflict-free RMWs).
// Blocks dump u16x2-packed partials to global scratch; the last block to
// finish each batch (atomic ticket) reduces that batch's partials, applies
// weights, writes the output, and resets the ticket (graph-replay safe).

constexpr int B = 32, S = 16384, F = 64, BINS = 128;
constexpr int NCHUNK = 27;             // 26*608 + 576 = 16384; iters<=152 (u8-safe)
constexpr int CHUNK = 608;
constexpr int THREADS = 256;
// smem: 8 warps x 1024 words. word(w, m, l) = w*1024 + m*32 + l  (bank = l)
constexpr int SMEM_BYTES = 8 * 1024 * 4;           // 32768 B -> 6 blocks/SM

// u16x2-packed partials: word W = q*64 + f holds bins (2q, 2q+1) of feature f.
constexpr int PWORDS = (BINS / 2) * F;             // 4096 words per (chunk,batch)
__device__ __align__(16) unsigned int g_scratch[(size_t)NCHUNK * B * PWORDS];
__device__ int g_count[B];                          // zero-initialized; reset by reducer

__global__ __launch_bounds__(THREADS, 6)
void hist_kernel(const float* __restrict__ x, const float* __restrict__ wts,
                 float* __restrict__ out) {
    extern __shared__ unsigned int sh[];
    __shared__ int s_last;
    const int tid = threadIdx.x;
    const int w = tid >> 5, l = tid & 31;

    // zero own histogram: word (w, m, l) -> bank l, conflict-free
#pragma unroll
    for (int m = 0; m < 32; m++) sh[(w << 10) + (m << 5) + l] = 0u;

    unsigned char* sb = reinterpret_cast<unsigned char*>(sh);
    const unsigned int tbase = (w << 12) + (l << 2);   // byte base of this lane's hist

    const int fh = w & 1;        // feature half: 0 -> f 0..31, 1 -> f 32..63
    const int soff = w >> 1;     // row offset mod 4
    const int f = fh * 32 + l;
    const int b = blockIdx.y, c = blockIdx.x;

    const int row0 = c * CHUNK;
    const int rows = min(CHUNK, S - row0);   // 608 or 576
    const int iters = rows >> 2;             // 152 or 144 (both /8) -> u8 safe
    const float* base = x + (((size_t)b * S + row0 + soff) * F + f);

    constexpr int U = 8;                     // load-ahead for MLP
#pragma unroll 1
    for (int i = 0; i < iters; i += U) {
        float v[U];
#pragma unroll
        for (int u = 0; u < U; u++)
            v[u] = __ldcs(base + (size_t)(i + u) * (4 * F));
#pragma unroll
        for (int u = 0; u < U; u++) {
            // exact trunc(v*128): RZ-add truncates mantissa; bin bits = [16:23)
            const unsigned int bits = __float_as_uint(__fadd_rz(v[u], 1.0f));
            // byte offset ((bin>>2)<<7) | (bin&3): keeps this lane in bank l
            const unsigned int off = (((bits >> 18) & 31u) << 7) | ((bits >> 16) & 3u);
            sb[tbase + off] = (unsigned char)(sb[tbase + off] + 1);
        }
    }
    __syncthreads();

    // Intra-block reduction over 4 s-offsets (dp4a byte extraction),
    // u16x2-packed coalesced dump. Loads hit bank fl = lane -> conflict-free.
    unsigned int* outp = g_scratch + ((size_t)c * B + b) * PWORDS;
#pragma unroll
    for (int k = 0; k < 8; k++) {
        const int u = tid + THREADS * k;     // 0..2047
        const int fo = u & 63;
        const int m  = u >> 6;               // -> bins 4m..4m+3
        const int fh2 = fo >> 5, fl = fo & 31;
        unsigned int s0 = 0, s1 = 0, s2 = 0, s3 = 0;
#pragma unroll
        for (int s = 0; s < 4; s++) {
            const unsigned int v = sh[((2 * s + fh2) << 10) + (m << 5) + fl];
            s0 = __dp4a(v, 0x00000001u, s0);
            s1 = __dp4a(v, 0x00000100u, s1);
            s2 = __dp4a(v, 0x00010000u, s2);
            s3 = __dp4a(v, 0x01000000u, s3);
        }
        outp[(2 * m + 0) * F + fo] = s0 | (s1 << 16);   // bins 4m, 4m+1
        outp[(2 * m + 1) * F + fo] = s2 | (s3 << 16);   // bins 4m+2, 4m+3
    }

    // ---- ticket: last block of this batch reduces it ----
    __threadfence();
    if (tid == 0)
        s_last = (atomicAdd(&g_count[b], 1) == NCHUNK - 1);
    __syncthreads();
    if (!s_last) return;
    __threadfence();   // acquire: all 27 dumps for batch b are visible

    // Reduce batch b: 4096 words, 16 per thread; loads & stores coalesced.
    const unsigned int* sc = g_scratch + (size_t)b * PWORDS;
#pragma unroll 1
    for (int k = 0; k < 16; k++) {
        const int W = tid + THREADS * k;     // q*64 + f
        const int q = W >> 6, fo = W & 63;
        unsigned int a = 0;
#pragma unroll
        for (int c2 = 0; c2 < NCHUNK; c2++)
            a += sc[(size_t)c2 * B * PWORDS + W];        // packed u16x2, carry-free
        const float wlo = wts[(2 * q) * F + fo];
        const float whi = wts[(2 * q + 1) * F + fo];
        float* ob = out + ((size_t)b * BINS + 2 * q) * F + fo;
        ob[0] = (float)(a & 0xFFFFu) * wlo;
        ob[F] = (float)(a >> 16) * whi;
    }
    if (tid == 0) g_count[b] = 0;            // reset for next graph replay
}

extern "C" void kernel_launch(void* const* d_in, const int* in_sizes, int n_in,
                              void* d_out, int out_size) {
    const float* x   = (const float*)d_in[0];
    const float* wts = (const float*)d_in[1];
    float* out = (float*)d_out;

    cudaFuncSetAttribute(hist_kernel, cudaFuncAttributeMaxDynamicSharedMemorySize, SMEM_BYTES);

    dim3 grid(NCHUNK, B);   // 27 x 32 = 864 blocks, single wave at occ 6
    hist_kernel<<<grid, THREADS, SMEM_BYTES>>>(x, wts, out);
}